// round 1
// baseline (speedup 1.0000x reference)
#include <cuda_runtime.h>
#include <mma.h>
#include <math.h>

using namespace nvcuda;

// Problem constants
#define DMODEL 768
#define SQ     128
#define TOK    256
#define ROWS   (SQ*TOK)      // 32768
#define NH     12
#define HD     64
#define BHN    (SQ*NH)       // 1536  (also = 128 windows * 12 heads)
#define DFF    3072

// ---------------------------------------------------------------------------
// Scratch (device globals; no allocation allowed)
// ---------------------------------------------------------------------------
__device__ float g_ln [(size_t)ROWS * DMODEL];
__device__ float g_q  [(size_t)ROWS * DMODEL];
__device__ float g_k  [(size_t)ROWS * DMODEL];
__device__ float g_v  [(size_t)ROWS * DMODEL];
__device__ float g_y  [(size_t)ROWS * DMODEL];
__device__ float g_x1 [(size_t)ROWS * DMODEL];
__device__ float g_x2 [(size_t)ROWS * DMODEL];
__device__ float g_s  [(size_t)BHN * TOK * TOK];     // attention scores
__device__ float g_mid[(size_t)ROWS * DFF];          // MLP hidden

// Window permutation: window w, window-token j -> global row in (B*T) space.
// w = b0*16 + hb*4 + wbi ; j = bt*16 + hh*4 + ww ;
// row = (b0*16+bt)*256 + (hb*4+hh)*16 + (wbi*4+ww)
__device__ __forceinline__ int wmap(int w, int j) {
    int b0 = w >> 4, hb = (w >> 2) & 3, wi = w & 3;
    int bt = j >> 4, hh = (j >> 2) & 3, ww = j & 3;
    return (((b0 << 4) + bt) << 8) + (((hb << 2) + hh) << 4) + ((wi << 2) + ww);
}

// ---------------------------------------------------------------------------
// LayerNorm: one block per row of 768
// ---------------------------------------------------------------------------
__global__ void ln_kernel(const float* __restrict__ X, const float* __restrict__ g,
                          const float* __restrict__ b, float* __restrict__ O)
{
    __shared__ float red[256];
    int row = blockIdx.x, tid = threadIdx.x;
    const float* xr = X + (size_t)row * DMODEL;
    float v0 = xr[tid], v1 = xr[tid + 256], v2 = xr[tid + 512];
    red[tid] = v0 + v1 + v2;
    __syncthreads();
    #pragma unroll
    for (int s = 128; s > 0; s >>= 1) { if (tid < s) red[tid] += red[tid + s]; __syncthreads(); }
    float mean = red[0] * (1.0f / 768.0f);
    __syncthreads();
    float d0 = v0 - mean, d1 = v1 - mean, d2 = v2 - mean;
    red[tid] = d0*d0 + d1*d1 + d2*d2;
    __syncthreads();
    #pragma unroll
    for (int s = 128; s > 0; s >>= 1) { if (tid < s) red[tid] += red[tid + s]; __syncthreads(); }
    float rstd = rsqrtf(red[0] * (1.0f / 768.0f) + 1e-5f);
    float* o = O + (size_t)row * DMODEL;
    o[tid]       = d0 * rstd * g[tid]       + b[tid];
    o[tid + 256] = d1 * rstd * g[tid + 256] + b[tid + 256];
    o[tid + 512] = d2 * rstd * g[tid + 512] + b[tid + 512];
}

// ---------------------------------------------------------------------------
// Generic TF32 wmma GEMM:  C[M,N] = A[M,K] @ B[K,N] + bias (+GELU) (+Res)
// Block tile 128x128, BK=32, 8 warps (4M x 2N), warp tile 32x64,
// wmma m16n16k8, fused epilogue via SMEM staging (two 64-col halves).
// Requires M%128==0, N%128==0, K%32==0 (all shapes here comply).
// ---------------------------------------------------------------------------
__global__ void gemm_kernel(const float* __restrict__ A, const float* __restrict__ B,
                            const float* __restrict__ bias, const float* __restrict__ Res,
                            float* __restrict__ C, int M, int N, int K, int do_gelu)
{
    __shared__ float sh[8832];           // max(As+Bs = 4608+4224, stag 128*68=8704)
    float* As = sh;                      // [128][36]
    float* Bs = sh + 128 * 36;           // [32][132]

    int tid = threadIdx.x;
    int warpId = tid >> 5;
    int wm = warpId & 3;                 // 0..3 along M
    int wn = warpId >> 2;                // 0..1 along N
    int rowBase = blockIdx.y * 128;
    int colBase = blockIdx.x * 128;

    wmma::fragment<wmma::accumulator, 16, 16, 8, float> acc[2][4];
    #pragma unroll
    for (int i = 0; i < 2; i++)
        #pragma unroll
        for (int j = 0; j < 4; j++) wmma::fill_fragment(acc[i][j], 0.0f);

    for (int kc = 0; kc < K; kc += 32) {
        #pragma unroll
        for (int i = 0; i < 4; i++) {
            int id = tid + i * 256;
            int r = id >> 3, c = (id & 7) * 4;
            *(float4*)&As[r * 36 + c] =
                *(const float4*)&A[(size_t)(rowBase + r) * K + kc + c];
        }
        #pragma unroll
        for (int i = 0; i < 4; i++) {
            int id = tid + i * 256;
            int r = id >> 5, c = (id & 31) * 4;
            *(float4*)&Bs[r * 132 + c] =
                *(const float4*)&B[(size_t)(kc + r) * N + colBase + c];
        }
        __syncthreads();
        #pragma unroll
        for (int kk = 0; kk < 4; kk++) {
            wmma::fragment<wmma::matrix_a, 16, 16, 8, wmma::precision::tf32, wmma::row_major> af[2];
            wmma::fragment<wmma::matrix_b, 16, 16, 8, wmma::precision::tf32, wmma::row_major> bf[4];
            #pragma unroll
            for (int i = 0; i < 2; i++) {
                wmma::load_matrix_sync(af[i], &As[(wm * 32 + i * 16) * 36 + kk * 8], 36);
                #pragma unroll
                for (int t = 0; t < af[i].num_elements; t++)
                    af[i].x[t] = wmma::__float_to_tf32(af[i].x[t]);
            }
            #pragma unroll
            for (int j = 0; j < 4; j++) {
                wmma::load_matrix_sync(bf[j], &Bs[kk * 8 * 132 + wn * 64 + j * 16], 132);
                #pragma unroll
                for (int t = 0; t < bf[j].num_elements; t++)
                    bf[j].x[t] = wmma::__float_to_tf32(bf[j].x[t]);
            }
            #pragma unroll
            for (int i = 0; i < 2; i++)
                #pragma unroll
                for (int j = 0; j < 4; j++)
                    wmma::mma_sync(acc[i][j], af[i], bf[j], acc[i][j]);
        }
        __syncthreads();
    }

    // Fused epilogue: stage each 64-col half in SMEM, apply bias/gelu/residual.
    float* stag = sh;                    // [128][68]
    for (int half = 0; half < 2; half++) {
        if (wn == half) {
            #pragma unroll
            for (int i = 0; i < 2; i++)
                #pragma unroll
                for (int j = 0; j < 4; j++)
                    wmma::store_matrix_sync(&stag[(wm * 32 + i * 16) * 68 + j * 16],
                                            acc[i][j], 68, wmma::mem_row_major);
        }
        __syncthreads();
        #pragma unroll
        for (int i = 0; i < 32; i++) {
            int id = tid + i * 256;
            int r = id >> 6, c = id & 63;
            int cg = colBase + half * 64 + c;
            size_t off = (size_t)(rowBase + r) * N + cg;
            float v = stag[r * 68 + c] + bias[cg];
            if (do_gelu) v = 0.5f * v * (1.0f + erff(v * 0.70710678118654752f));
            if (Res) v += Res[off];
            C[off] = v;
        }
        __syncthreads();
    }
}

// ---------------------------------------------------------------------------
// Batched attention scores: S[bh, t, s] = Q[t,:] . K[s,:]  (per head slice)
// grid.x: 4 tiles (2x2 of 128), grid.y: 1536 (b,h) pairs / (window,h) pairs
// ---------------------------------------------------------------------------
template<bool WIN>
__global__ void score_kernel(const float* __restrict__ Q, const float* __restrict__ Kmat,
                             float* __restrict__ S)
{
    __shared__ float sh[9216];
    float* Qs = sh;              // [128][36]
    float* Ks = sh + 4608;       // [128][36]  (rows = s, cols = d)
    int tid = threadIdx.x;
    int warpId = tid >> 5, wm = warpId & 3, wn = warpId >> 2;
    int bh = blockIdx.y;
    int b = bh / NH, h = bh % NH;
    int tx = blockIdx.x & 1, ty = blockIdx.x >> 1;

    wmma::fragment<wmma::accumulator, 16, 16, 8, float> acc[2][4];
    #pragma unroll
    for (int i = 0; i < 2; i++)
        #pragma unroll
        for (int j = 0; j < 4; j++) wmma::fill_fragment(acc[i][j], 0.0f);

    for (int kc = 0; kc < HD; kc += 32) {
        #pragma unroll
        for (int i = 0; i < 4; i++) {
            int id = tid + i * 256;
            int r = id >> 3, c = (id & 7) * 4;
            int t = ty * 128 + r;
            int grow = WIN ? wmap(b, t) : (b * TOK + t);
            *(float4*)&Qs[r * 36 + c] =
                *(const float4*)&Q[(size_t)grow * DMODEL + h * HD + kc + c];
        }
        #pragma unroll
        for (int i = 0; i < 4; i++) {
            int id = tid + i * 256;
            int r = id >> 3, c = (id & 7) * 4;
            int s = tx * 128 + r;
            int grow = WIN ? wmap(b, s) : (b * TOK + s);
            *(float4*)&Ks[r * 36 + c] =
                *(const float4*)&Kmat[(size_t)grow * DMODEL + h * HD + kc + c];
        }
        __syncthreads();
        #pragma unroll
        for (int kk = 0; kk < 4; kk++) {
            wmma::fragment<wmma::matrix_a, 16, 16, 8, wmma::precision::tf32, wmma::row_major> af[2];
            wmma::fragment<wmma::matrix_b, 16, 16, 8, wmma::precision::tf32, wmma::col_major> bf[4];
            #pragma unroll
            for (int i = 0; i < 2; i++) {
                wmma::load_matrix_sync(af[i], &Qs[(wm * 32 + i * 16) * 36 + kk * 8], 36);
                #pragma unroll
                for (int t = 0; t < af[i].num_elements; t++)
                    af[i].x[t] = wmma::__float_to_tf32(af[i].x[t]);
            }
            #pragma unroll
            for (int j = 0; j < 4; j++) {
                wmma::load_matrix_sync(bf[j], &Ks[(wn * 64 + j * 16) * 36 + kk * 8], 36);
                #pragma unroll
                for (int t = 0; t < bf[j].num_elements; t++)
                    bf[j].x[t] = wmma::__float_to_tf32(bf[j].x[t]);
            }
            #pragma unroll
            for (int i = 0; i < 2; i++)
                #pragma unroll
                for (int j = 0; j < 4; j++)
                    wmma::mma_sync(acc[i][j], af[i], bf[j], acc[i][j]);
        }
        __syncthreads();
    }
    size_t base = (size_t)bh * (TOK * TOK);
    #pragma unroll
    for (int i = 0; i < 2; i++)
        #pragma unroll
        for (int j = 0; j < 4; j++)
            wmma::store_matrix_sync(
                &S[base + (size_t)(ty * 128 + wm * 32 + i * 16) * TOK
                       + tx * 128 + wn * 64 + j * 16],
                acc[i][j], TOK, wmma::mem_row_major);
}

// ---------------------------------------------------------------------------
// Softmax over 256-long rows of S (scale + optional mask fused)
// ---------------------------------------------------------------------------
__global__ void softmax_kernel(float* __restrict__ S, const int* __restrict__ mask)
{
    __shared__ float red[256];
    int row = blockIdx.x, tid = threadIdx.x;
    int t = row & 255;
    size_t idx = (size_t)row * 256 + tid;
    float v = S[idx] * 0.125f;                       // 1/sqrt(64)
    if (mask && mask[t * 256 + tid] == 0) v = -INFINITY;
    red[tid] = v;
    __syncthreads();
    #pragma unroll
    for (int s = 128; s > 0; s >>= 1) { if (tid < s) red[tid] = fmaxf(red[tid], red[tid + s]); __syncthreads(); }
    float mx = red[0];
    __syncthreads();
    float e = expf(v - mx);
    red[tid] = e;
    __syncthreads();
    #pragma unroll
    for (int s = 128; s > 0; s >>= 1) { if (tid < s) red[tid] += red[tid + s]; __syncthreads(); }
    S[idx] = e / red[0];
}

// ---------------------------------------------------------------------------
// Batched PV: Y[t, h*64:+64] = sum_s P[t,s] * V[s, h*64:+64]
// Block tile 128x64, BK=32, warp tile 32x32, scatter rows on store (window).
// grid.x: 2 (M tiles), grid.y: 1536
// ---------------------------------------------------------------------------
template<bool WIN>
__global__ void pv_kernel(const float* __restrict__ S, const float* __restrict__ V,
                          float* __restrict__ Y)
{
    __shared__ float sh[8704];           // max(As+Bs = 4608+2176, stag 128*68)
    float* As = sh;                      // [128][36]
    float* Bs = sh + 4608;               // [32][68]
    int tid = threadIdx.x;
    int warpId = tid >> 5, wm = warpId & 3, wn = warpId >> 2;
    int bh = blockIdx.y;
    int b = bh / NH, h = bh % NH;
    int ty = blockIdx.x;

    wmma::fragment<wmma::accumulator, 16, 16, 8, float> acc[2][2];
    #pragma unroll
    for (int i = 0; i < 2; i++)
        #pragma unroll
        for (int j = 0; j < 2; j++) wmma::fill_fragment(acc[i][j], 0.0f);

    size_t sbase = (size_t)bh * (TOK * TOK);
    for (int kc = 0; kc < TOK; kc += 32) {
        #pragma unroll
        for (int i = 0; i < 4; i++) {
            int id = tid + i * 256;
            int r = id >> 3, c = (id & 7) * 4;
            *(float4*)&As[r * 36 + c] =
                *(const float4*)&S[sbase + (size_t)(ty * 128 + r) * TOK + kc + c];
        }
        #pragma unroll
        for (int i = 0; i < 2; i++) {
            int id = tid + i * 256;
            int r = id >> 4, c = (id & 15) * 4;
            int s = kc + r;
            int grow = WIN ? wmap(b, s) : (b * TOK + s);
            *(float4*)&Bs[r * 68 + c] =
                *(const float4*)&V[(size_t)grow * DMODEL + h * HD + c];
        }
        __syncthreads();
        #pragma unroll
        for (int kk = 0; kk < 4; kk++) {
            wmma::fragment<wmma::matrix_a, 16, 16, 8, wmma::precision::tf32, wmma::row_major> af[2];
            wmma::fragment<wmma::matrix_b, 16, 16, 8, wmma::precision::tf32, wmma::row_major> bf[2];
            #pragma unroll
            for (int i = 0; i < 2; i++) {
                wmma::load_matrix_sync(af[i], &As[(wm * 32 + i * 16) * 36 + kk * 8], 36);
                #pragma unroll
                for (int t = 0; t < af[i].num_elements; t++)
                    af[i].x[t] = wmma::__float_to_tf32(af[i].x[t]);
            }
            #pragma unroll
            for (int j = 0; j < 2; j++) {
                wmma::load_matrix_sync(bf[j], &Bs[(kk * 8) * 68 + wn * 32 + j * 16], 68);
                #pragma unroll
                for (int t = 0; t < bf[j].num_elements; t++)
                    bf[j].x[t] = wmma::__float_to_tf32(bf[j].x[t]);
            }
            #pragma unroll
            for (int i = 0; i < 2; i++)
                #pragma unroll
                for (int j = 0; j < 2; j++)
                    wmma::mma_sync(acc[i][j], af[i], bf[j], acc[i][j]);
        }
        __syncthreads();
    }

    // Stage to SMEM, then scatter rows to global (window_reverse fused here)
    float* stag = sh;                    // [128][68]
    #pragma unroll
    for (int i = 0; i < 2; i++)
        #pragma unroll
        for (int j = 0; j < 2; j++)
            wmma::store_matrix_sync(&stag[(wm * 32 + i * 16) * 68 + wn * 32 + j * 16],
                                    acc[i][j], 68, wmma::mem_row_major);
    __syncthreads();
    #pragma unroll
    for (int i = 0; i < 32; i++) {
        int id = tid + i * 256;
        int r = id >> 6, c = id & 63;
        int t = ty * 128 + r;
        int grow = WIN ? wmap(b, t) : (b * TOK + t);
        Y[(size_t)grow * DMODEL + h * HD + c] = stag[r * 68 + c];
    }
}

// ---------------------------------------------------------------------------
// Launch sequence
// ---------------------------------------------------------------------------
extern "C" void kernel_launch(void* const* d_in, const int* in_sizes, int n_in,
                              void* d_out, int out_size)
{
    (void)in_sizes; (void)n_in; (void)out_size;
    const float* x    = (const float*)d_in[0];
    const int*   mask = (const int*)  d_in[1];
    const float* ln1g = (const float*)d_in[2];
    const float* ln1b = (const float*)d_in[3];
    const float* ln2g = (const float*)d_in[4];
    const float* ln2b = (const float*)d_in[5];
    const float* ln3g = (const float*)d_in[6];
    const float* ln3b = (const float*)d_in[7];
    const float* q1w = (const float*)d_in[8];  const float* q1b = (const float*)d_in[9];
    const float* k1w = (const float*)d_in[10]; const float* k1b = (const float*)d_in[11];
    const float* v1w = (const float*)d_in[12]; const float* v1b = (const float*)d_in[13];
    const float* o1w = (const float*)d_in[14]; const float* o1b = (const float*)d_in[15];
    const float* q2w = (const float*)d_in[16]; const float* q2b = (const float*)d_in[17];
    const float* k2w = (const float*)d_in[18]; const float* k2b = (const float*)d_in[19];
    const float* v2w = (const float*)d_in[20]; const float* v2b = (const float*)d_in[21];
    const float* o2w = (const float*)d_in[22]; const float* o2b = (const float*)d_in[23];
    const float* f1w = (const float*)d_in[24]; const float* f1b = (const float*)d_in[25];
    const float* f2w = (const float*)d_in[26]; const float* f2b = (const float*)d_in[27];
    float* out = (float*)d_out;

    float *ln, *q, *k, *v, *y, *x1, *x2, *s, *mid;
    cudaGetSymbolAddress((void**)&ln,  g_ln);
    cudaGetSymbolAddress((void**)&q,   g_q);
    cudaGetSymbolAddress((void**)&k,   g_k);
    cudaGetSymbolAddress((void**)&v,   g_v);
    cudaGetSymbolAddress((void**)&y,   g_y);
    cudaGetSymbolAddress((void**)&x1,  g_x1);
    cudaGetSymbolAddress((void**)&x2,  g_x2);
    cudaGetSymbolAddress((void**)&s,   g_s);
    cudaGetSymbolAddress((void**)&mid, g_mid);

    dim3 blk(256);
    dim3 gD(DMODEL / 128, ROWS / 128);   // (6, 256)
    dim3 gF1(DFF / 128, ROWS / 128);     // (24, 256)

    // ---- Block 1: full attention ----
    ln_kernel<<<ROWS, 256>>>(x, ln1g, ln1b, ln);
    gemm_kernel<<<gD, blk>>>(ln, q1w, q1b, nullptr, q, ROWS, DMODEL, DMODEL, 0);
    gemm_kernel<<<gD, blk>>>(ln, k1w, k1b, nullptr, k, ROWS, DMODEL, DMODEL, 0);
    gemm_kernel<<<gD, blk>>>(ln, v1w, v1b, nullptr, v, ROWS, DMODEL, DMODEL, 0);
    score_kernel<false><<<dim3(4, BHN), blk>>>(q, k, s);
    softmax_kernel<<<BHN * TOK, 256>>>(s, mask);
    pv_kernel<false><<<dim3(2, BHN), blk>>>(s, v, y);
    gemm_kernel<<<gD, blk>>>(y, o1w, o1b, x, x1, ROWS, DMODEL, DMODEL, 0);

    // ---- Block 2: window attention (permutation handled by index map) ----
    ln_kernel<<<ROWS, 256>>>(x1, ln2g, ln2b, ln);
    gemm_kernel<<<gD, blk>>>(ln, q2w, q2b, nullptr, q, ROWS, DMODEL, DMODEL, 0);
    gemm_kernel<<<gD, blk>>>(ln, k2w, k2b, nullptr, k, ROWS, DMODEL, DMODEL, 0);
    gemm_kernel<<<gD, blk>>>(ln, v2w, v2b, nullptr, v, ROWS, DMODEL, DMODEL, 0);
    score_kernel<true><<<dim3(4, BHN), blk>>>(q, k, s);
    softmax_kernel<<<BHN * TOK, 256>>>(s, nullptr);
    pv_kernel<true><<<dim3(2, BHN), blk>>>(s, v, y);
    gemm_kernel<<<gD, blk>>>(y, o2w, o2b, x1, x2, ROWS, DMODEL, DMODEL, 0);

    // ---- MLP ----
    ln_kernel<<<ROWS, 256>>>(x2, ln3g, ln3b, ln);
    gemm_kernel<<<gF1, blk>>>(ln, f1w, f1b, nullptr, mid, ROWS, DFF, DMODEL, 1);
    gemm_kernel<<<gD, blk>>>(mid, f2w, f2b, x2, out, ROWS, DMODEL, DFF, 0);
}

// round 3
// speedup vs baseline: 1.1604x; 1.1604x over previous
#include <cuda_runtime.h>
#include <mma.h>
#include <math.h>
#include <stdint.h>

using namespace nvcuda;

// Problem constants
#define DMODEL 768
#define SQ     128
#define TOK    256
#define ROWS   (SQ*TOK)      // 32768
#define NH     12
#define HD     64
#define BHN    (SQ*NH)       // 1536
#define DFF    3072

// ---------------------------------------------------------------------------
// Scratch (device globals; no allocation allowed)
// ---------------------------------------------------------------------------
__device__ float g_ln [(size_t)ROWS * DMODEL];
__device__ float g_q  [(size_t)ROWS * DMODEL];
__device__ float g_k  [(size_t)ROWS * DMODEL];
__device__ float g_v  [(size_t)ROWS * DMODEL];
__device__ float g_y  [(size_t)ROWS * DMODEL];
__device__ float g_x1 [(size_t)ROWS * DMODEL];
__device__ float g_x2 [(size_t)ROWS * DMODEL];
__device__ float g_s  [(size_t)BHN * TOK * TOK];     // attention scores
__device__ float g_mid[(size_t)ROWS * DFF];          // MLP hidden

// ---------------------------------------------------------------------------
// cp.async helpers
// ---------------------------------------------------------------------------
__device__ __forceinline__ uint32_t smem_u32(const void* p) {
    uint32_t a;
    asm("{ .reg .u64 t; cvta.to.shared.u64 t, %1; cvt.u32.u64 %0, t; }" : "=r"(a) : "l"(p));
    return a;
}
__device__ __forceinline__ void cpasync16(uint32_t dst, const void* src) {
    asm volatile("cp.async.cg.shared.global [%0], [%1], 16;\n" :: "r"(dst), "l"(src));
}
__device__ __forceinline__ void cp_commit() { asm volatile("cp.async.commit_group;\n" ::); }
template<int N> __device__ __forceinline__ void cp_wait() {
    asm volatile("cp.async.wait_group %0;\n" :: "n"(N));
}

// Window permutation: window w, window-token j -> global row in (B*T) space.
__device__ __forceinline__ int wmap(int w, int j) {
    int b0 = w >> 4, hb = (w >> 2) & 3, wi = w & 3;
    int bt = j >> 4, hh = (j >> 2) & 3, ww = j & 3;
    return (((b0 << 4) + bt) << 8) + (((hb << 2) + hh) << 4) + ((wi << 2) + ww);
}

// ---------------------------------------------------------------------------
// LayerNorm: one block per row of 768
// ---------------------------------------------------------------------------
__global__ void ln_kernel(const float* __restrict__ X, const float* __restrict__ g,
                          const float* __restrict__ b, float* __restrict__ O)
{
    __shared__ float red[256];
    int row = blockIdx.x, tid = threadIdx.x;
    const float* xr = X + (size_t)row * DMODEL;
    float v0 = xr[tid], v1 = xr[tid + 256], v2 = xr[tid + 512];
    red[tid] = v0 + v1 + v2;
    __syncthreads();
    #pragma unroll
    for (int s = 128; s > 0; s >>= 1) { if (tid < s) red[tid] += red[tid + s]; __syncthreads(); }
    float mean = red[0] * (1.0f / 768.0f);
    __syncthreads();
    float d0 = v0 - mean, d1 = v1 - mean, d2 = v2 - mean;
    red[tid] = d0*d0 + d1*d1 + d2*d2;
    __syncthreads();
    #pragma unroll
    for (int s = 128; s > 0; s >>= 1) { if (tid < s) red[tid] += red[tid + s]; __syncthreads(); }
    float rstd = rsqrtf(red[0] * (1.0f / 768.0f) + 1e-5f);
    float* o = O + (size_t)row * DMODEL;
    o[tid]       = d0 * rstd * g[tid]       + b[tid];
    o[tid + 256] = d1 * rstd * g[tid + 256] + b[tid + 256];
    o[tid + 512] = d2 * rstd * g[tid + 512] + b[tid + 512];
}

// ---------------------------------------------------------------------------
// Pipelined TF32 wmma GEMM:  C[M,N] = A[M,K] @ B[K,N] + bias (+GELU) (+Res)
// CTA tile 128x128, BK=32, 3-stage cp.async pipeline, 8 warps (4Mx2N),
// warp tile 32x64, register double-buffered fragments, fused epilogue.
// Requires M%128==0, N%128==0, K%32==0, K/32 >= 3.
// ---------------------------------------------------------------------------
#define NSTG 3
#define STG_F 8832                    // floats per stage: As 128*36 + Bs 32*132
#define GEMM_DSMEM (NSTG * STG_F * 4) // 105984 bytes

__device__ __forceinline__ void g_loadA(float* As, const float* __restrict__ A,
                                        int rowBase, int kc, int K)
{
    int tid = threadIdx.x;
    uint32_t base = smem_u32(As);
    #pragma unroll
    for (int i = 0; i < 4; i++) {
        int id = tid + i * 256;
        int r = id >> 3, c = (id & 7) * 4;
        cpasync16(base + (uint32_t)(r * 36 + c) * 4,
                  A + (size_t)(rowBase + r) * K + kc + c);
    }
}
__device__ __forceinline__ void g_loadB(float* Bs, const float* __restrict__ B,
                                        int colBase, int kc, int N)
{
    int tid = threadIdx.x;
    uint32_t base = smem_u32(Bs);
    #pragma unroll
    for (int i = 0; i < 4; i++) {
        int id = tid + i * 256;
        int r = id >> 5, c = (id & 31) * 4;
        cpasync16(base + (uint32_t)(r * 132 + c) * 4,
                  B + (size_t)(kc + r) * N + colBase + c);
    }
}

typedef wmma::fragment<wmma::matrix_a, 16, 16, 8, wmma::precision::tf32, wmma::row_major> AF;
typedef wmma::fragment<wmma::matrix_b, 16, 16, 8, wmma::precision::tf32, wmma::row_major> BF;

__device__ __forceinline__ void ldA(AF* a, const float* As, int wm, int kk) {
    #pragma unroll
    for (int i = 0; i < 2; i++) {
        wmma::load_matrix_sync(a[i], &As[(wm * 32 + i * 16) * 36 + kk * 8], 36);
        #pragma unroll
        for (int t = 0; t < a[i].num_elements; t++)
            a[i].x[t] = wmma::__float_to_tf32(a[i].x[t]);
    }
}
__device__ __forceinline__ void ldB(BF* b, const float* Bs, int wn, int kk) {
    #pragma unroll
    for (int j = 0; j < 4; j++) {
        wmma::load_matrix_sync(b[j], &Bs[kk * 8 * 132 + wn * 64 + j * 16], 132);
        #pragma unroll
        for (int t = 0; t < b[j].num_elements; t++)
            b[j].x[t] = wmma::__float_to_tf32(b[j].x[t]);
    }
}

__global__ void __launch_bounds__(256, 1)
gemm_kernel(const float* __restrict__ A, const float* __restrict__ B,
            const float* __restrict__ bias, const float* __restrict__ Res,
            float* __restrict__ C, int M, int N, int K, int do_gelu)
{
    extern __shared__ __align__(16) float sh[];

    int tid = threadIdx.x;
    int warpId = tid >> 5;
    int wm = warpId & 3;                 // 0..3 along M
    int wn = warpId >> 2;                // 0..1 along N
    int rowBase = blockIdx.y * 128;
    int colBase = blockIdx.x * 128;

    wmma::fragment<wmma::accumulator, 16, 16, 8, float> acc[2][4];
    #pragma unroll
    for (int i = 0; i < 2; i++)
        #pragma unroll
        for (int j = 0; j < 4; j++) wmma::fill_fragment(acc[i][j], 0.0f);

    int nk = K / 32;

    // Prologue: fill stages 0..NSTG-2
    #pragma unroll
    for (int s = 0; s < NSTG - 1; s++) {
        g_loadA(sh + s * STG_F,        A, rowBase, s * 32, K);
        g_loadB(sh + s * STG_F + 4608, B, colBase, s * 32, N);
        cp_commit();
    }

    for (int kc = 0; kc < nk; kc++) {
        int buf = kc % NSTG;
        float* As = sh + buf * STG_F;
        float* Bs = As + 4608;

        cp_wait<NSTG - 2>();             // stage kc resident
        __syncthreads();                 // also: everyone done computing kc-1

        int pf = kc + NSTG - 1;
        if (pf < nk) {
            int pbuf = pf % NSTG;
            g_loadA(sh + pbuf * STG_F,        A, rowBase, pf * 32, K);
            g_loadB(sh + pbuf * STG_F + 4608, B, colBase, pf * 32, N);
        }
        cp_commit();

        // Compute 4 k8 steps with register double-buffering
        AF af[2][2]; BF bf[2][4];
        ldA(af[0], As, wm, 0);
        ldB(bf[0], Bs, wn, 0);
        #pragma unroll
        for (int kk = 0; kk < 4; kk++) {
            int cur = kk & 1, nxt = cur ^ 1;
            if (kk < 3) { ldA(af[nxt], As, wm, kk + 1); ldB(bf[nxt], Bs, wn, kk + 1); }
            #pragma unroll
            for (int i = 0; i < 2; i++)
                #pragma unroll
                for (int j = 0; j < 4; j++)
                    wmma::mma_sync(acc[i][j], af[cur][i], bf[cur][j], acc[i][j]);
        }
    }
    __syncthreads();                     // all compute done before stag reuse

    // Fused epilogue: stage each 64-col half in SMEM, apply bias/gelu/residual.
    float* stag = sh;                    // [128][68]
    for (int half = 0; half < 2; half++) {
        if (wn == half) {
            #pragma unroll
            for (int i = 0; i < 2; i++)
                #pragma unroll
                for (int j = 0; j < 4; j++)
                    wmma::store_matrix_sync(&stag[(wm * 32 + i * 16) * 68 + j * 16],
                                            acc[i][j], 68, wmma::mem_row_major);
        }
        __syncthreads();
        #pragma unroll
        for (int i = 0; i < 8; i++) {
            int id = tid + i * 256;      // 0..2047 -> 128 rows x 16 float4
            int r = id >> 4, j = id & 15;
            int cg = colBase + half * 64 + j * 4;
            size_t off = (size_t)(rowBase + r) * N + cg;
            float4 v = *(float4*)&stag[r * 68 + j * 4];
            float4 bb = *(const float4*)&bias[cg];
            v.x += bb.x; v.y += bb.y; v.z += bb.z; v.w += bb.w;
            if (do_gelu) {
                v.x = 0.5f * v.x * (1.0f + erff(v.x * 0.70710678118654752f));
                v.y = 0.5f * v.y * (1.0f + erff(v.y * 0.70710678118654752f));
                v.z = 0.5f * v.z * (1.0f + erff(v.z * 0.70710678118654752f));
                v.w = 0.5f * v.w * (1.0f + erff(v.w * 0.70710678118654752f));
            }
            if (Res) {
                float4 rv = *(const float4*)&Res[off];
                v.x += rv.x; v.y += rv.y; v.z += rv.z; v.w += rv.w;
            }
            *(float4*)&C[off] = v;
        }
        __syncthreads();
    }
}

// ---------------------------------------------------------------------------
// Batched attention scores: S[bh, t, s] = Q[t,:] . K[s,:]  (per head slice)
// ---------------------------------------------------------------------------
template<bool WIN>
__global__ void score_kernel(const float* __restrict__ Q, const float* __restrict__ Kmat,
                             float* __restrict__ S)
{
    __shared__ float sh[9216];
    float* Qs = sh;              // [128][36]
    float* Ks = sh + 4608;       // [128][36]
    int tid = threadIdx.x;
    int warpId = tid >> 5, wm = warpId & 3, wn = warpId >> 2;
    int bh = blockIdx.y;
    int b = bh / NH, h = bh % NH;
    int tx = blockIdx.x & 1, ty = blockIdx.x >> 1;

    wmma::fragment<wmma::accumulator, 16, 16, 8, float> acc[2][4];
    #pragma unroll
    for (int i = 0; i < 2; i++)
        #pragma unroll
        for (int j = 0; j < 4; j++) wmma::fill_fragment(acc[i][j], 0.0f);

    for (int kc = 0; kc < HD; kc += 32) {
        #pragma unroll
        for (int i = 0; i < 4; i++) {
            int id = tid + i * 256;
            int r = id >> 3, c = (id & 7) * 4;
            int t = ty * 128 + r;
            int grow = WIN ? wmap(b, t) : (b * TOK + t);
            *(float4*)&Qs[r * 36 + c] =
                *(const float4*)&Q[(size_t)grow * DMODEL + h * HD + kc + c];
        }
        #pragma unroll
        for (int i = 0; i < 4; i++) {
            int id = tid + i * 256;
            int r = id >> 3, c = (id & 7) * 4;
            int s = tx * 128 + r;
            int grow = WIN ? wmap(b, s) : (b * TOK + s);
            *(float4*)&Ks[r * 36 + c] =
                *(const float4*)&Kmat[(size_t)grow * DMODEL + h * HD + kc + c];
        }
        __syncthreads();
        #pragma unroll
        for (int kk = 0; kk < 4; kk++) {
            wmma::fragment<wmma::matrix_a, 16, 16, 8, wmma::precision::tf32, wmma::row_major> af[2];
            wmma::fragment<wmma::matrix_b, 16, 16, 8, wmma::precision::tf32, wmma::col_major> bf[4];
            #pragma unroll
            for (int i = 0; i < 2; i++) {
                wmma::load_matrix_sync(af[i], &Qs[(wm * 32 + i * 16) * 36 + kk * 8], 36);
                #pragma unroll
                for (int t = 0; t < af[i].num_elements; t++)
                    af[i].x[t] = wmma::__float_to_tf32(af[i].x[t]);
            }
            #pragma unroll
            for (int j = 0; j < 4; j++) {
                wmma::load_matrix_sync(bf[j], &Ks[(wn * 64 + j * 16) * 36 + kk * 8], 36);
                #pragma unroll
                for (int t = 0; t < bf[j].num_elements; t++)
                    bf[j].x[t] = wmma::__float_to_tf32(bf[j].x[t]);
            }
            #pragma unroll
            for (int i = 0; i < 2; i++)
                #pragma unroll
                for (int j = 0; j < 4; j++)
                    wmma::mma_sync(acc[i][j], af[i], bf[j], acc[i][j]);
        }
        __syncthreads();
    }
    size_t base = (size_t)bh * (TOK * TOK);
    #pragma unroll
    for (int i = 0; i < 2; i++)
        #pragma unroll
        for (int j = 0; j < 4; j++)
            wmma::store_matrix_sync(
                &S[base + (size_t)(ty * 128 + wm * 32 + i * 16) * TOK
                       + tx * 128 + wn * 64 + j * 16],
                acc[i][j], TOK, wmma::mem_row_major);
}

// ---------------------------------------------------------------------------
// Softmax over 256-long rows (warp-shuffle two-level reduction)
// ---------------------------------------------------------------------------
__global__ void softmax_kernel(float* __restrict__ S, const int* __restrict__ mask)
{
    __shared__ float wred[8];
    int row = blockIdx.x, tid = threadIdx.x, lane = tid & 31, wrp = tid >> 5;
    int t = row & 255;
    size_t idx = (size_t)row * 256 + tid;
    float v = S[idx] * 0.125f;
    if (mask && mask[t * 256 + tid] == 0) v = -INFINITY;
    float m = v;
    #pragma unroll
    for (int o = 16; o > 0; o >>= 1) m = fmaxf(m, __shfl_xor_sync(0xffffffffu, m, o));
    if (lane == 0) wred[wrp] = m;
    __syncthreads();
    float mx = wred[lane & 7];
    #pragma unroll
    for (int o = 4; o > 0; o >>= 1) mx = fmaxf(mx, __shfl_xor_sync(0xffffffffu, mx, o));
    float e = __expf(v - mx);
    float sum = e;
    #pragma unroll
    for (int o = 16; o > 0; o >>= 1) sum += __shfl_xor_sync(0xffffffffu, sum, o);
    __syncthreads();
    if (lane == 0) wred[wrp] = sum;
    __syncthreads();
    float ts = wred[lane & 7];
    #pragma unroll
    for (int o = 4; o > 0; o >>= 1) ts += __shfl_xor_sync(0xffffffffu, ts, o);
    S[idx] = e / ts;
}

// ---------------------------------------------------------------------------
// Batched PV with fused window scatter
// ---------------------------------------------------------------------------
template<bool WIN>
__global__ void pv_kernel(const float* __restrict__ S, const float* __restrict__ V,
                          float* __restrict__ Y)
{
    __shared__ float sh[8704];
    float* As = sh;                      // [128][36]
    float* Bs = sh + 4608;               // [32][68]
    int tid = threadIdx.x;
    int warpId = tid >> 5, wm = warpId & 3, wn = warpId >> 2;
    int bh = blockIdx.y;
    int b = bh / NH, h = bh % NH;
    int ty = blockIdx.x;

    wmma::fragment<wmma::accumulator, 16, 16, 8, float> acc[2][2];
    #pragma unroll
    for (int i = 0; i < 2; i++)
        #pragma unroll
        for (int j = 0; j < 2; j++) wmma::fill_fragment(acc[i][j], 0.0f);

    size_t sbase = (size_t)bh * (TOK * TOK);
    for (int kc = 0; kc < TOK; kc += 32) {
        #pragma unroll
        for (int i = 0; i < 4; i++) {
            int id = tid + i * 256;
            int r = id >> 3, c = (id & 7) * 4;
            *(float4*)&As[r * 36 + c] =
                *(const float4*)&S[sbase + (size_t)(ty * 128 + r) * TOK + kc + c];
        }
        #pragma unroll
        for (int i = 0; i < 2; i++) {
            int id = tid + i * 256;
            int r = id >> 4, c = (id & 15) * 4;
            int s = kc + r;
            int grow = WIN ? wmap(b, s) : (b * TOK + s);
            *(float4*)&Bs[r * 68 + c] =
                *(const float4*)&V[(size_t)grow * DMODEL + h * HD + c];
        }
        __syncthreads();
        #pragma unroll
        for (int kk = 0; kk < 4; kk++) {
            wmma::fragment<wmma::matrix_a, 16, 16, 8, wmma::precision::tf32, wmma::row_major> af[2];
            wmma::fragment<wmma::matrix_b, 16, 16, 8, wmma::precision::tf32, wmma::row_major> bf[2];
            #pragma unroll
            for (int i = 0; i < 2; i++) {
                wmma::load_matrix_sync(af[i], &As[(wm * 32 + i * 16) * 36 + kk * 8], 36);
                #pragma unroll
                for (int t = 0; t < af[i].num_elements; t++)
                    af[i].x[t] = wmma::__float_to_tf32(af[i].x[t]);
            }
            #pragma unroll
            for (int j = 0; j < 2; j++) {
                wmma::load_matrix_sync(bf[j], &Bs[(kk * 8) * 68 + wn * 32 + j * 16], 68);
                #pragma unroll
                for (int t = 0; t < bf[j].num_elements; t++)
                    bf[j].x[t] = wmma::__float_to_tf32(bf[j].x[t]);
            }
            #pragma unroll
            for (int i = 0; i < 2; i++)
                #pragma unroll
                for (int j = 0; j < 2; j++)
                    wmma::mma_sync(acc[i][j], af[i], bf[j], acc[i][j]);
        }
        __syncthreads();
    }

    float* stag = sh;                    // [128][68]
    #pragma unroll
    for (int i = 0; i < 2; i++)
        #pragma unroll
        for (int j = 0; j < 2; j++)
            wmma::store_matrix_sync(&stag[(wm * 32 + i * 16) * 68 + wn * 32 + j * 16],
                                    acc[i][j], 68, wmma::mem_row_major);
    __syncthreads();
    #pragma unroll
    for (int i = 0; i < 32; i++) {
        int id = tid + i * 256;
        int r = id >> 6, c = id & 63;
        int t = ty * 128 + r;
        int grow = WIN ? wmap(b, t) : (b * TOK + t);
        Y[(size_t)grow * DMODEL + h * HD + c] = stag[r * 68 + c];
    }
}

// ---------------------------------------------------------------------------
// Launch sequence
// ---------------------------------------------------------------------------
extern "C" void kernel_launch(void* const* d_in, const int* in_sizes, int n_in,
                              void* d_out, int out_size)
{
    (void)in_sizes; (void)n_in; (void)out_size;
    const float* x    = (const float*)d_in[0];
    const int*   mask = (const int*)  d_in[1];
    const float* ln1g = (const float*)d_in[2];
    const float* ln1b = (const float*)d_in[3];
    const float* ln2g = (const float*)d_in[4];
    const float* ln2b = (const float*)d_in[5];
    const float* ln3g = (const float*)d_in[6];
    const float* ln3b = (const float*)d_in[7];
    const float* q1w = (const float*)d_in[8];  const float* q1b = (const float*)d_in[9];
    const float* k1w = (const float*)d_in[10]; const float* k1b = (const float*)d_in[11];
    const float* v1w = (const float*)d_in[12]; const float* v1b = (const float*)d_in[13];
    const float* o1w = (const float*)d_in[14]; const float* o1b = (const float*)d_in[15];
    const float* q2w = (const float*)d_in[16]; const float* q2b = (const float*)d_in[17];
    const float* k2w = (const float*)d_in[18]; const float* k2b = (const float*)d_in[19];
    const float* v2w = (const float*)d_in[20]; const float* v2b = (const float*)d_in[21];
    const float* o2w = (const float*)d_in[22]; const float* o2b = (const float*)d_in[23];
    const float* f1w = (const float*)d_in[24]; const float* f1b = (const float*)d_in[25];
    const float* f2w = (const float*)d_in[26]; const float* f2b = (const float*)d_in[27];
    float* out = (float*)d_out;

    float *ln, *q, *k, *v, *y, *x1, *x2, *s, *mid;
    cudaGetSymbolAddress((void**)&ln,  g_ln);
    cudaGetSymbolAddress((void**)&q,   g_q);
    cudaGetSymbolAddress((void**)&k,   g_k);
    cudaGetSymbolAddress((void**)&v,   g_v);
    cudaGetSymbolAddress((void**)&y,   g_y);
    cudaGetSymbolAddress((void**)&x1,  g_x1);
    cudaGetSymbolAddress((void**)&x2,  g_x2);
    cudaGetSymbolAddress((void**)&s,   g_s);
    cudaGetSymbolAddress((void**)&mid, g_mid);

    cudaFuncSetAttribute(gemm_kernel, cudaFuncAttributeMaxDynamicSharedMemorySize, GEMM_DSMEM);

    dim3 blk(256);
    dim3 gD(DMODEL / 128, ROWS / 128);   // (6, 256)
    dim3 gF1(DFF / 128, ROWS / 128);     // (24, 256)

    // ---- Block 1: full attention ----
    ln_kernel<<<ROWS, 256>>>(x, ln1g, ln1b, ln);
    gemm_kernel<<<gD, blk, GEMM_DSMEM>>>(ln, q1w, q1b, nullptr, q, ROWS, DMODEL, DMODEL, 0);
    gemm_kernel<<<gD, blk, GEMM_DSMEM>>>(ln, k1w, k1b, nullptr, k, ROWS, DMODEL, DMODEL, 0);
    gemm_kernel<<<gD, blk, GEMM_DSMEM>>>(ln, v1w, v1b, nullptr, v, ROWS, DMODEL, DMODEL, 0);
    score_kernel<false><<<dim3(4, BHN), blk>>>(q, k, s);
    softmax_kernel<<<BHN * TOK, 256>>>(s, mask);
    pv_kernel<false><<<dim3(2, BHN), blk>>>(s, v, y);
    gemm_kernel<<<gD, blk, GEMM_DSMEM>>>(y, o1w, o1b, x, x1, ROWS, DMODEL, DMODEL, 0);

    // ---- Block 2: window attention (permutation via index map) ----
    ln_kernel<<<ROWS, 256>>>(x1, ln2g, ln2b, ln);
    gemm_kernel<<<gD, blk, GEMM_DSMEM>>>(ln, q2w, q2b, nullptr, q, ROWS, DMODEL, DMODEL, 0);
    gemm_kernel<<<gD, blk, GEMM_DSMEM>>>(ln, k2w, k2b, nullptr, k, ROWS, DMODEL, DMODEL, 0);
    gemm_kernel<<<gD, blk, GEMM_DSMEM>>>(ln, v2w, v2b, nullptr, v, ROWS, DMODEL, DMODEL, 0);
    score_kernel<true><<<dim3(4, BHN), blk>>>(q, k, s);
    softmax_kernel<<<BHN * TOK, 256>>>(s, nullptr);
    pv_kernel<true><<<dim3(2, BHN), blk>>>(s, v, y);
    gemm_kernel<<<gD, blk, GEMM_DSMEM>>>(y, o2w, o2b, x1, x2, ROWS, DMODEL, DMODEL, 0);

    // ---- MLP ----
    ln_kernel<<<ROWS, 256>>>(x2, ln3g, ln3b, ln);
    gemm_kernel<<<gF1, blk, GEMM_DSMEM>>>(ln, f1w, f1b, nullptr, mid, ROWS, DFF, DMODEL, 1);
    gemm_kernel<<<gD, blk, GEMM_DSMEM>>>(mid, f2w, f2b, x2, out, ROWS, DMODEL, DFF, 0);
}

// round 4
// speedup vs baseline: 1.2464x; 1.0741x over previous
#include <cuda_runtime.h>
#include <mma.h>
#include <math.h>
#include <stdint.h>

using namespace nvcuda;

// Problem constants
#define DMODEL 768
#define SQ     128
#define TOK    256
#define ROWS   (SQ*TOK)      // 32768
#define NH     12
#define HD     64
#define BHN    (SQ*NH)       // 1536
#define DFF    3072

// ---------------------------------------------------------------------------
// Scratch (device globals; no allocation allowed)
// ---------------------------------------------------------------------------
__device__ float g_ln [(size_t)ROWS * DMODEL];
__device__ float g_q  [(size_t)ROWS * DMODEL];
__device__ float g_k  [(size_t)ROWS * DMODEL];
__device__ float g_v  [(size_t)ROWS * DMODEL];
__device__ float g_y  [(size_t)ROWS * DMODEL];
__device__ float g_x1 [(size_t)ROWS * DMODEL];
__device__ float g_x2 [(size_t)ROWS * DMODEL];
__device__ float g_s  [(size_t)BHN * TOK * TOK];     // attention scores
__device__ float g_mid[(size_t)ROWS * DFF];          // MLP hidden
__device__ float g_wt [9437184];                     // tf32-rounded weights

#define WT_D(i) ((size_t)(i) * 589824)               // 8 x 768*768
#define WT_F1   ((size_t)4718592)                    // 768*3072
#define WT_F2   ((size_t)7077888)                    // 3072*768

// ---------------------------------------------------------------------------
// helpers
// ---------------------------------------------------------------------------
__device__ __forceinline__ uint32_t smem_u32(const void* p) {
    uint32_t a;
    asm("{ .reg .u64 t; cvta.to.shared.u64 t, %1; cvt.u32.u64 %0, t; }" : "=r"(a) : "l"(p));
    return a;
}
__device__ __forceinline__ void cpasync16(uint32_t dst, const void* src) {
    asm volatile("cp.async.cg.shared.global [%0], [%1], 16;\n" :: "r"(dst), "l"(src));
}
__device__ __forceinline__ void cp_commit() { asm volatile("cp.async.commit_group;\n" ::); }
template<int N> __device__ __forceinline__ void cp_wait() {
    asm volatile("cp.async.wait_group %0;\n" :: "n"(N));
}
__device__ __forceinline__ float rtf(float x) { return wmma::__float_to_tf32(x); }

// Window permutation: window w, window-token j -> global row in (B*T) space.
__device__ __forceinline__ int wmap(int w, int j) {
    int b0 = w >> 4, hb = (w >> 2) & 3, wi = w & 3;
    int bt = j >> 4, hh = (j >> 2) & 3, ww = j & 3;
    return (((b0 << 4) + bt) << 8) + (((hb << 2) + hh) << 4) + ((wi << 2) + ww);
}

// ---------------------------------------------------------------------------
// Weight pre-round (tf32) copy
// ---------------------------------------------------------------------------
__global__ void round_kernel(const float* __restrict__ W, float* __restrict__ O, int n)
{
    int i = blockIdx.x * 256 + threadIdx.x;
    if (i * 4 < n) {
        float4 v = *(const float4*)&W[i * 4];
        v.x = rtf(v.x); v.y = rtf(v.y); v.z = rtf(v.z); v.w = rtf(v.w);
        *(float4*)&O[i * 4] = v;
    }
}

// ---------------------------------------------------------------------------
// LayerNorm: one block per row of 768; output pre-rounded to tf32
// (g_ln is consumed only as GEMM A operand)
// ---------------------------------------------------------------------------
__global__ void ln_kernel(const float* __restrict__ X, const float* __restrict__ g,
                          const float* __restrict__ b, float* __restrict__ O)
{
    __shared__ float red[256];
    int row = blockIdx.x, tid = threadIdx.x;
    const float* xr = X + (size_t)row * DMODEL;
    float v0 = xr[tid], v1 = xr[tid + 256], v2 = xr[tid + 512];
    red[tid] = v0 + v1 + v2;
    __syncthreads();
    #pragma unroll
    for (int s = 128; s > 0; s >>= 1) { if (tid < s) red[tid] += red[tid + s]; __syncthreads(); }
    float mean = red[0] * (1.0f / 768.0f);
    __syncthreads();
    float d0 = v0 - mean, d1 = v1 - mean, d2 = v2 - mean;
    red[tid] = d0*d0 + d1*d1 + d2*d2;
    __syncthreads();
    #pragma unroll
    for (int s = 128; s > 0; s >>= 1) { if (tid < s) red[tid] += red[tid + s]; __syncthreads(); }
    float rstd = rsqrtf(red[0] * (1.0f / 768.0f) + 1e-5f);
    float* o = O + (size_t)row * DMODEL;
    o[tid]       = rtf(d0 * rstd * g[tid]       + b[tid]);
    o[tid + 256] = rtf(d1 * rstd * g[tid + 256] + b[tid + 256]);
    o[tid + 512] = rtf(d2 * rstd * g[tid + 512] + b[tid + 512]);
}

// ---------------------------------------------------------------------------
// Pipelined TF32 wmma GEMM:  C[M,N] = A[M,K] @ B[K,N] + bias (+GELU) (+Res)
// CTA tile 128x256, BK=32, 3-stage cp.async pipeline, 16 warps (4Mx4N),
// warp tile 32x64. Inputs pre-rounded to tf32 -> NO cvt in the mainloop.
// flags: bit0 = gelu, bit1 = round output to tf32 (output feeds a GEMM).
// ---------------------------------------------------------------------------
#define NSTG 3
#define AS_F  (128 * 36)               // 4608
#define BS_F  (32 * 264)               // 8448
#define STG_F (AS_F + BS_F)            // 13056 floats
#define GEMM_DSMEM (NSTG * STG_F * 4)  // 156672 bytes

__device__ __forceinline__ void g_loadA(float* As, const float* __restrict__ A,
                                        int rowBase, int kc, int K)
{
    int tid = threadIdx.x;
    uint32_t base = smem_u32(As);
    #pragma unroll
    for (int i = 0; i < 2; i++) {
        int id = tid + i * 512;
        int r = id >> 3, c = (id & 7) * 4;
        cpasync16(base + (uint32_t)(r * 36 + c) * 4,
                  A + (size_t)(rowBase + r) * K + kc + c);
    }
}
__device__ __forceinline__ void g_loadB(float* Bs, const float* __restrict__ B,
                                        int colBase, int kc, int N)
{
    int tid = threadIdx.x;
    uint32_t base = smem_u32(Bs);
    #pragma unroll
    for (int i = 0; i < 4; i++) {
        int id = tid + i * 512;
        int r = id >> 6, c = (id & 63) * 4;
        cpasync16(base + (uint32_t)(r * 264 + c) * 4,
                  B + (size_t)(kc + r) * N + colBase + c);
    }
}

typedef wmma::fragment<wmma::matrix_a, 16, 16, 8, wmma::precision::tf32, wmma::row_major> AF;
typedef wmma::fragment<wmma::matrix_b, 16, 16, 8, wmma::precision::tf32, wmma::row_major> BF;

__global__ void __launch_bounds__(512, 1)
gemm_kernel(const float* __restrict__ A, const float* __restrict__ B,
            const float* __restrict__ bias, const float* __restrict__ Res,
            float* __restrict__ C, int M, int N, int K, int flags)
{
    extern __shared__ __align__(16) float sh[];

    int tid = threadIdx.x;
    int warpId = tid >> 5;
    int wm = warpId & 3;                 // 0..3 along M (32 rows each)
    int wn = warpId >> 2;                // 0..3 along N (64 cols each)
    int rowBase = blockIdx.y * 128;
    int colBase = blockIdx.x * 256;

    wmma::fragment<wmma::accumulator, 16, 16, 8, float> acc[2][4];
    #pragma unroll
    for (int i = 0; i < 2; i++)
        #pragma unroll
        for (int j = 0; j < 4; j++) wmma::fill_fragment(acc[i][j], 0.0f);

    int nk = K / 32;

    #pragma unroll
    for (int s = 0; s < NSTG - 1; s++) {
        g_loadA(sh + s * STG_F,        A, rowBase, s * 32, K);
        g_loadB(sh + s * STG_F + AS_F, B, colBase, s * 32, N);
        cp_commit();
    }

    for (int kc = 0; kc < nk; kc++) {
        int buf = kc % NSTG;
        float* As = sh + buf * STG_F;
        float* Bs = As + AS_F;

        cp_wait<NSTG - 2>();
        __syncthreads();

        int pf = kc + NSTG - 1;
        if (pf < nk) {
            int pbuf = pf % NSTG;
            g_loadA(sh + pbuf * STG_F,        A, rowBase, pf * 32, K);
            g_loadB(sh + pbuf * STG_F + AS_F, B, colBase, pf * 32, N);
        }
        cp_commit();

        #pragma unroll
        for (int kk = 0; kk < 4; kk++) {
            AF af[2]; BF bf[4];
            #pragma unroll
            for (int i = 0; i < 2; i++)
                wmma::load_matrix_sync(af[i], &As[(wm * 32 + i * 16) * 36 + kk * 8], 36);
            #pragma unroll
            for (int j = 0; j < 4; j++)
                wmma::load_matrix_sync(bf[j], &Bs[kk * 8 * 264 + wn * 64 + j * 16], 264);
            #pragma unroll
            for (int i = 0; i < 2; i++)
                #pragma unroll
                for (int j = 0; j < 4; j++)
                    wmma::mma_sync(acc[i][j], af[i], bf[j], acc[i][j]);
        }
    }
    __syncthreads();

    // Epilogue: 4 quarters of 64 cols, staged via SMEM.
    float* stag = sh;                    // [128][68]
    int do_gelu = flags & 1, do_round = flags & 2;
    for (int qq = 0; qq < 4; qq++) {
        if (wn == qq) {
            #pragma unroll
            for (int i = 0; i < 2; i++)
                #pragma unroll
                for (int j = 0; j < 4; j++)
                    wmma::store_matrix_sync(&stag[(wm * 32 + i * 16) * 68 + j * 16],
                                            acc[i][j], 68, wmma::mem_row_major);
        }
        __syncthreads();
        #pragma unroll
        for (int i = 0; i < 4; i++) {
            int id = tid + i * 512;      // 0..2047 -> 128 rows x 16 float4
            int r = id >> 4, j = id & 15;
            int cg = colBase + qq * 64 + j * 4;
            size_t off = (size_t)(rowBase + r) * N + cg;
            float4 v = *(float4*)&stag[r * 68 + j * 4];
            float4 bb = *(const float4*)&bias[cg];
            v.x += bb.x; v.y += bb.y; v.z += bb.z; v.w += bb.w;
            if (do_gelu) {
                v.x = 0.5f * v.x * (1.0f + erff(v.x * 0.70710678118654752f));
                v.y = 0.5f * v.y * (1.0f + erff(v.y * 0.70710678118654752f));
                v.z = 0.5f * v.z * (1.0f + erff(v.z * 0.70710678118654752f));
                v.w = 0.5f * v.w * (1.0f + erff(v.w * 0.70710678118654752f));
            }
            if (Res) {
                float4 rv = *(const float4*)&Res[off];
                v.x += rv.x; v.y += rv.y; v.z += rv.z; v.w += rv.w;
            }
            if (do_round) { v.x = rtf(v.x); v.y = rtf(v.y); v.z = rtf(v.z); v.w = rtf(v.w); }
            *(float4*)&C[off] = v;
        }
        __syncthreads();
    }
}

// ---------------------------------------------------------------------------
// Batched attention scores: S[bh, t, s] = Q[t,:] . K[s,:]  (per head slice)
// Q/K are pre-rounded tf32 (GEMM epilogue round) -> no cvt here either.
// ---------------------------------------------------------------------------
template<bool WIN>
__global__ void score_kernel(const float* __restrict__ Q, const float* __restrict__ Kmat,
                             float* __restrict__ S)
{
    __shared__ float sh[9216];
    float* Qs = sh;              // [128][36]
    float* Ks = sh + 4608;       // [128][36]
    int tid = threadIdx.x;
    int warpId = tid >> 5, wm = warpId & 3, wn = warpId >> 2;
    int bh = blockIdx.y;
    int b = bh / NH, h = bh % NH;
    int tx = blockIdx.x & 1, ty = blockIdx.x >> 1;

    wmma::fragment<wmma::accumulator, 16, 16, 8, float> acc[2][4];
    #pragma unroll
    for (int i = 0; i < 2; i++)
        #pragma unroll
        for (int j = 0; j < 4; j++) wmma::fill_fragment(acc[i][j], 0.0f);

    for (int kc = 0; kc < HD; kc += 32) {
        #pragma unroll
        for (int i = 0; i < 4; i++) {
            int id = tid + i * 256;
            int r = id >> 3, c = (id & 7) * 4;
            int t = ty * 128 + r;
            int grow = WIN ? wmap(b, t) : (b * TOK + t);
            *(float4*)&Qs[r * 36 + c] =
                *(const float4*)&Q[(size_t)grow * DMODEL + h * HD + kc + c];
        }
        #pragma unroll
        for (int i = 0; i < 4; i++) {
            int id = tid + i * 256;
            int r = id >> 3, c = (id & 7) * 4;
            int s = tx * 128 + r;
            int grow = WIN ? wmap(b, s) : (b * TOK + s);
            *(float4*)&Ks[r * 36 + c] =
                *(const float4*)&Kmat[(size_t)grow * DMODEL + h * HD + kc + c];
        }
        __syncthreads();
        #pragma unroll
        for (int kk = 0; kk < 4; kk++) {
            wmma::fragment<wmma::matrix_a, 16, 16, 8, wmma::precision::tf32, wmma::row_major> af[2];
            wmma::fragment<wmma::matrix_b, 16, 16, 8, wmma::precision::tf32, wmma::col_major> bf[4];
            #pragma unroll
            for (int i = 0; i < 2; i++)
                wmma::load_matrix_sync(af[i], &Qs[(wm * 32 + i * 16) * 36 + kk * 8], 36);
            #pragma unroll
            for (int j = 0; j < 4; j++)
                wmma::load_matrix_sync(bf[j], &Ks[(wn * 64 + j * 16) * 36 + kk * 8], 36);
            #pragma unroll
            for (int i = 0; i < 2; i++)
                #pragma unroll
                for (int j = 0; j < 4; j++)
                    wmma::mma_sync(acc[i][j], af[i], bf[j], acc[i][j]);
        }
        __syncthreads();
    }
    size_t base = (size_t)bh * (TOK * TOK);
    #pragma unroll
    for (int i = 0; i < 2; i++)
        #pragma unroll
        for (int j = 0; j < 4; j++)
            wmma::store_matrix_sync(
                &S[base + (size_t)(ty * 128 + wm * 32 + i * 16) * TOK
                       + tx * 128 + wn * 64 + j * 16],
                acc[i][j], TOK, wmma::mem_row_major);
}

// ---------------------------------------------------------------------------
// Softmax over 256-long rows (warp-shuffle two-level reduction)
// Output rounded to tf32 (feeds pv wmma directly).
// ---------------------------------------------------------------------------
__global__ void softmax_kernel(float* __restrict__ S, const int* __restrict__ mask)
{
    __shared__ float wred[8];
    int row = blockIdx.x, tid = threadIdx.x, lane = tid & 31, wrp = tid >> 5;
    int t = row & 255;
    size_t idx = (size_t)row * 256 + tid;
    float v = S[idx] * 0.125f;
    if (mask && mask[t * 256 + tid] == 0) v = -INFINITY;
    float m = v;
    #pragma unroll
    for (int o = 16; o > 0; o >>= 1) m = fmaxf(m, __shfl_xor_sync(0xffffffffu, m, o));
    if (lane == 0) wred[wrp] = m;
    __syncthreads();
    float mx = wred[lane & 7];
    #pragma unroll
    for (int o = 4; o > 0; o >>= 1) mx = fmaxf(mx, __shfl_xor_sync(0xffffffffu, mx, o));
    float e = __expf(v - mx);
    float sum = e;
    #pragma unroll
    for (int o = 16; o > 0; o >>= 1) sum += __shfl_xor_sync(0xffffffffu, sum, o);
    __syncthreads();
    if (lane == 0) wred[wrp] = sum;
    __syncthreads();
    float ts = wred[lane & 7];
    #pragma unroll
    for (int o = 4; o > 0; o >>= 1) ts += __shfl_xor_sync(0xffffffffu, ts, o);
    S[idx] = rtf(e / ts);
}

// ---------------------------------------------------------------------------
// Batched PV with fused window scatter. S and V pre-rounded -> no cvt.
// Output rounded (feeds O-projection GEMM).
// ---------------------------------------------------------------------------
template<bool WIN>
__global__ void pv_kernel(const float* __restrict__ S, const float* __restrict__ V,
                          float* __restrict__ Y)
{
    __shared__ float sh[8704];
    float* As = sh;                      // [128][36]
    float* Bs = sh + 4608;               // [32][68]
    int tid = threadIdx.x;
    int warpId = tid >> 5, wm = warpId & 3, wn = warpId >> 2;
    int bh = blockIdx.y;
    int b = bh / NH, h = bh % NH;
    int ty = blockIdx.x;

    wmma::fragment<wmma::accumulator, 16, 16, 8, float> acc[2][2];
    #pragma unroll
    for (int i = 0; i < 2; i++)
        #pragma unroll
        for (int j = 0; j < 2; j++) wmma::fill_fragment(acc[i][j], 0.0f);

    size_t sbase = (size_t)bh * (TOK * TOK);
    for (int kc = 0; kc < TOK; kc += 32) {
        #pragma unroll
        for (int i = 0; i < 4; i++) {
            int id = tid + i * 256;
            int r = id >> 3, c = (id & 7) * 4;
            *(float4*)&As[r * 36 + c] =
                *(const float4*)&S[sbase + (size_t)(ty * 128 + r) * TOK + kc + c];
        }
        #pragma unroll
        for (int i = 0; i < 2; i++) {
            int id = tid + i * 256;
            int r = id >> 4, c = (id & 15) * 4;
            int s = kc + r;
            int grow = WIN ? wmap(b, s) : (b * TOK + s);
            *(float4*)&Bs[r * 68 + c] =
                *(const float4*)&V[(size_t)grow * DMODEL + h * HD + c];
        }
        __syncthreads();
        #pragma unroll
        for (int kk = 0; kk < 4; kk++) {
            wmma::fragment<wmma::matrix_a, 16, 16, 8, wmma::precision::tf32, wmma::row_major> af[2];
            wmma::fragment<wmma::matrix_b, 16, 16, 8, wmma::precision::tf32, wmma::row_major> bf[2];
            #pragma unroll
            for (int i = 0; i < 2; i++)
                wmma::load_matrix_sync(af[i], &As[(wm * 32 + i * 16) * 36 + kk * 8], 36);
            #pragma unroll
            for (int j = 0; j < 2; j++)
                wmma::load_matrix_sync(bf[j], &Bs[(kk * 8) * 68 + wn * 32 + j * 16], 68);
            #pragma unroll
            for (int i = 0; i < 2; i++)
                #pragma unroll
                for (int j = 0; j < 2; j++)
                    wmma::mma_sync(acc[i][j], af[i], bf[j], acc[i][j]);
        }
        __syncthreads();
    }

    float* stag = sh;                    // [128][68]
    #pragma unroll
    for (int i = 0; i < 2; i++)
        #pragma unroll
        for (int j = 0; j < 2; j++)
            wmma::store_matrix_sync(&stag[(wm * 32 + i * 16) * 68 + wn * 32 + j * 16],
                                    acc[i][j], 68, wmma::mem_row_major);
    __syncthreads();
    #pragma unroll
    for (int i = 0; i < 32; i++) {
        int id = tid + i * 256;
        int r = id >> 6, c = id & 63;
        int t = ty * 128 + r;
        int grow = WIN ? wmap(b, t) : (b * TOK + t);
        Y[(size_t)grow * DMODEL + h * HD + c] = rtf(stag[r * 68 + c]);
    }
}

// ---------------------------------------------------------------------------
// Launch sequence
// ---------------------------------------------------------------------------
extern "C" void kernel_launch(void* const* d_in, const int* in_sizes, int n_in,
                              void* d_out, int out_size)
{
    (void)in_sizes; (void)n_in; (void)out_size;
    const float* x    = (const float*)d_in[0];
    const int*   mask = (const int*)  d_in[1];
    const float* ln1g = (const float*)d_in[2];
    const float* ln1b = (const float*)d_in[3];
    const float* ln2g = (const float*)d_in[4];
    const float* ln2b = (const float*)d_in[5];
    const float* ln3g = (const float*)d_in[6];
    const float* ln3b = (const float*)d_in[7];
    const float* q1w = (const float*)d_in[8];  const float* q1b = (const float*)d_in[9];
    const float* k1w = (const float*)d_in[10]; const float* k1b = (const float*)d_in[11];
    const float* v1w = (const float*)d_in[12]; const float* v1b = (const float*)d_in[13];
    const float* o1w = (const float*)d_in[14]; const float* o1b = (const float*)d_in[15];
    const float* q2w = (const float*)d_in[16]; const float* q2b = (const float*)d_in[17];
    const float* k2w = (const float*)d_in[18]; const float* k2b = (const float*)d_in[19];
    const float* v2w = (const float*)d_in[20]; const float* v2b = (const float*)d_in[21];
    const float* o2w = (const float*)d_in[22]; const float* o2b = (const float*)d_in[23];
    const float* f1w = (const float*)d_in[24]; const float* f1b = (const float*)d_in[25];
    const float* f2w = (const float*)d_in[26]; const float* f2b = (const float*)d_in[27];
    float* out = (float*)d_out;

    float *ln, *q, *k, *v, *y, *x1, *x2, *s, *mid, *wt;
    cudaGetSymbolAddress((void**)&ln,  g_ln);
    cudaGetSymbolAddress((void**)&q,   g_q);
    cudaGetSymbolAddress((void**)&k,   g_k);
    cudaGetSymbolAddress((void**)&v,   g_v);
    cudaGetSymbolAddress((void**)&y,   g_y);
    cudaGetSymbolAddress((void**)&x1,  g_x1);
    cudaGetSymbolAddress((void**)&x2,  g_x2);
    cudaGetSymbolAddress((void**)&s,   g_s);
    cudaGetSymbolAddress((void**)&mid, g_mid);
    cudaGetSymbolAddress((void**)&wt,  g_wt);

    cudaFuncSetAttribute(gemm_kernel, cudaFuncAttributeMaxDynamicSharedMemorySize, GEMM_DSMEM);

    // Pre-round all weights to tf32 (idempotent w.r.t. in-loop conversion)
    const float* Ws[8] = {q1w, k1w, v1w, o1w, q2w, k2w, v2w, o2w};
    for (int i = 0; i < 8; i++)
        round_kernel<<<589824 / 1024, 256>>>(Ws[i], wt + WT_D(i), 589824);
    round_kernel<<<2359296 / 1024, 256>>>(f1w, wt + WT_F1, 2359296);
    round_kernel<<<2359296 / 1024, 256>>>(f2w, wt + WT_F2, 2359296);

    dim3 blk5(512);
    dim3 blk(256);
    dim3 gD(DMODEL / 256, ROWS / 128);   // (3, 256)
    dim3 gF1(DFF / 256, ROWS / 128);     // (12, 256)

    // flags: 1 = gelu, 2 = round output (output is a GEMM/MMA input)
    // ---- Block 1: full attention ----
    ln_kernel<<<ROWS, 256>>>(x, ln1g, ln1b, ln);
    gemm_kernel<<<gD, blk5, GEMM_DSMEM>>>(ln, wt + WT_D(0), q1b, nullptr, q, ROWS, DMODEL, DMODEL, 2);
    gemm_kernel<<<gD, blk5, GEMM_DSMEM>>>(ln, wt + WT_D(1), k1b, nullptr, k, ROWS, DMODEL, DMODEL, 2);
    gemm_kernel<<<gD, blk5, GEMM_DSMEM>>>(ln, wt + WT_D(2), v1b, nullptr, v, ROWS, DMODEL, DMODEL, 2);
    score_kernel<false><<<dim3(4, BHN), blk>>>(q, k, s);
    softmax_kernel<<<BHN * TOK, 256>>>(s, mask);
    pv_kernel<false><<<dim3(2, BHN), blk>>>(s, v, y);
    gemm_kernel<<<gD, blk5, GEMM_DSMEM>>>(y, wt + WT_D(3), o1b, x, x1, ROWS, DMODEL, DMODEL, 0);

    // ---- Block 2: window attention (permutation via index map) ----
    ln_kernel<<<ROWS, 256>>>(x1, ln2g, ln2b, ln);
    gemm_kernel<<<gD, blk5, GEMM_DSMEM>>>(ln, wt + WT_D(4), q2b, nullptr, q, ROWS, DMODEL, DMODEL, 2);
    gemm_kernel<<<gD, blk5, GEMM_DSMEM>>>(ln, wt + WT_D(5), k2b, nullptr, k, ROWS, DMODEL, DMODEL, 2);
    gemm_kernel<<<gD, blk5, GEMM_DSMEM>>>(ln, wt + WT_D(6), v2b, nullptr, v, ROWS, DMODEL, DMODEL, 2);
    score_kernel<true><<<dim3(4, BHN), blk>>>(q, k, s);
    softmax_kernel<<<BHN * TOK, 256>>>(s, nullptr);
    pv_kernel<true><<<dim3(2, BHN), blk>>>(s, v, y);
    gemm_kernel<<<gD, blk5, GEMM_DSMEM>>>(y, wt + WT_D(7), o2b, x1, x2, ROWS, DMODEL, DMODEL, 0);

    // ---- MLP ----
    ln_kernel<<<ROWS, 256>>>(x2, ln3g, ln3b, ln);
    gemm_kernel<<<gF1, blk5, GEMM_DSMEM>>>(ln, wt + WT_F1, f1b, nullptr, mid, ROWS, DFF, DMODEL, 3);
    gemm_kernel<<<gD, blk5, GEMM_DSMEM>>>(mid, wt + WT_F2, f2b, x2, out, ROWS, DMODEL, DFF, 0);
}

// round 9
// speedup vs baseline: 3.0124x; 2.4170x over previous
#include <cuda_runtime.h>
#include <cuda_fp16.h>
#include <mma.h>
#include <math.h>
#include <stdint.h>

using namespace nvcuda;

// Problem constants
#define DMODEL 768
#define SQ     128
#define TOK    256
#define ROWS   (SQ*TOK)      // 32768
#define NH     12
#define HD     64
#define BHN    (SQ*NH)       // 1536
#define DFF    3072

// ---------------------------------------------------------------------------
// Scratch (device globals; no allocation allowed). All 16B-aligned.
// ---------------------------------------------------------------------------
__device__ __align__(16) __half g_ln [(size_t)ROWS * DMODEL];
__device__ __align__(16) float  g_q  [(size_t)ROWS * DMODEL];
__device__ __align__(16) float  g_k  [(size_t)ROWS * DMODEL];
__device__ __align__(16) float  g_v  [(size_t)ROWS * DMODEL];
__device__ __align__(16) __half g_y  [(size_t)ROWS * DMODEL];
__device__ __align__(16) __half g_mid[(size_t)ROWS * DFF];
__device__ __align__(16) float  g_s  [(size_t)BHN * TOK * TOK];
__device__ __align__(16) float  g_x1 [(size_t)ROWS * DMODEL];
__device__ __align__(16) float  g_x2 [(size_t)ROWS * DMODEL];
__device__ __align__(16) __half g_wt [9437184];      // all weights, half

#define WT_D(i) ((size_t)(i) * 589824)               // 8 x 768*768
#define WT_F1   ((size_t)4718592)                    // [768][3072]
#define WT_F2   ((size_t)7077888)                    // [3072][768]

// ---------------------------------------------------------------------------
// helpers
// ---------------------------------------------------------------------------
__device__ __forceinline__ uint32_t smem_u32(const void* p) {
    uint32_t a;
    asm("{ .reg .u64 t; cvta.to.shared.u64 t, %1; cvt.u32.u64 %0, t; }" : "=r"(a) : "l"(p));
    return a;
}
__device__ __forceinline__ void cpasync16(uint32_t dst, const void* src) {
    asm volatile("cp.async.cg.shared.global [%0], [%1], 16;\n" :: "r"(dst), "l"(src));
}
__device__ __forceinline__ void cp_commit() { asm volatile("cp.async.commit_group;\n" ::); }
template<int N> __device__ __forceinline__ void cp_wait() {
    asm volatile("cp.async.wait_group %0;\n" :: "n"(N));
}
__device__ __forceinline__ uint2 pack4h(float a, float b, float c, float d) {
    __half2 lo = __floats2half2_rn(a, b), hi = __floats2half2_rn(c, d);
    uint2 r; r.x = *(uint32_t*)&lo; r.y = *(uint32_t*)&hi; return r;
}
__device__ __forceinline__ float rtf(float x) { return wmma::__float_to_tf32(x); }

// Window permutation: window w, window-token j -> global row in (B*T) space.
__device__ __forceinline__ int wmap(int w, int j) {
    int b0 = w >> 4, hb = (w >> 2) & 3, wi = w & 3;
    int bt = j >> 4, hh = (j >> 2) & 3, ww = j & 3;
    return (((b0 << 4) + bt) << 8) + (((hb << 2) + hh) << 4) + ((wi << 2) + ww);
}

// ---------------------------------------------------------------------------
// Weight convert to half
// ---------------------------------------------------------------------------
__global__ void cvt_half(const float* __restrict__ W, __half* __restrict__ O, int n4)
{
    int i = blockIdx.x * 256 + threadIdx.x;
    if (i < n4) {
        float4 v = *(const float4*)&W[i * 4];
        *(uint2*)&O[i * 4] = pack4h(v.x, v.y, v.z, v.w);
    }
}

// ---------------------------------------------------------------------------
// LayerNorm: one block per row of 768; writes half (GEMM A operand only)
// ---------------------------------------------------------------------------
__global__ void ln_kernel(const float* __restrict__ X, const float* __restrict__ g,
                          const float* __restrict__ b, __half* __restrict__ O)
{
    __shared__ float red[256];
    int row = blockIdx.x, tid = threadIdx.x;
    const float* xr = X + (size_t)row * DMODEL;
    float v0 = xr[tid], v1 = xr[tid + 256], v2 = xr[tid + 512];
    red[tid] = v0 + v1 + v2;
    __syncthreads();
    #pragma unroll
    for (int s = 128; s > 0; s >>= 1) { if (tid < s) red[tid] += red[tid + s]; __syncthreads(); }
    float mean = red[0] * (1.0f / 768.0f);
    __syncthreads();
    float d0 = v0 - mean, d1 = v1 - mean, d2 = v2 - mean;
    red[tid] = d0*d0 + d1*d1 + d2*d2;
    __syncthreads();
    #pragma unroll
    for (int s = 128; s > 0; s >>= 1) { if (tid < s) red[tid] += red[tid + s]; __syncthreads(); }
    float rstd = rsqrtf(red[0] * (1.0f / 768.0f) + 1e-5f);
    __half* o = O + (size_t)row * DMODEL;
    o[tid]       = __float2half_rn(d0 * rstd * g[tid]       + b[tid]);
    o[tid + 256] = __float2half_rn(d1 * rstd * g[tid + 256] + b[tid + 256]);
    o[tid + 512] = __float2half_rn(d2 * rstd * g[tid + 512] + b[tid + 512]);
}

// ---------------------------------------------------------------------------
// Pipelined FP16 wmma GEMM:  C[M,N] = A[M,K] @ B[K,N] + bias (+GELU) (+Res)
// CTA tile 128x256, BK=64, 3-stage cp.async pipeline, 16 warps (4Mx4N),
// warp tile 32x64, wmma m16n16k16, fp32 accum.
// flags: bit0 gelu, bit1 half out, bit2 tf32-round fp32 out.
// ---------------------------------------------------------------------------
#define NSTG 3
#define AS_H  (128 * 72)               // halves
#define BS_H  (64 * 264)
#define STG_H (AS_H + BS_H)            // 26112 halves = 52224 B
#define GEMM_DSMEM (NSTG * STG_H * 2)  // 156672 B

__device__ __forceinline__ void g_loadA(__half* As, const __half* __restrict__ A,
                                        int rowBase, int kc, int K)
{
    int tid = threadIdx.x;
    uint32_t base = smem_u32(As);
    #pragma unroll
    for (int i = 0; i < 2; i++) {
        int id = tid + i * 512;              // 0..1023
        int r = id >> 3, c8 = id & 7;
        cpasync16(base + (uint32_t)(r * 72 + c8 * 8) * 2,
                  A + (size_t)(rowBase + r) * K + kc + c8 * 8);
    }
}
__device__ __forceinline__ void g_loadB(__half* Bs, const __half* __restrict__ B,
                                        int colBase, int kc, int N)
{
    int tid = threadIdx.x;
    uint32_t base = smem_u32(Bs);
    #pragma unroll
    for (int i = 0; i < 4; i++) {
        int id = tid + i * 512;              // 0..2047
        int r = id >> 5, c8 = id & 31;
        cpasync16(base + (uint32_t)(r * 264 + c8 * 8) * 2,
                  B + (size_t)(kc + r) * N + colBase + c8 * 8);
    }
}

typedef wmma::fragment<wmma::matrix_a, 16, 16, 16, __half, wmma::row_major> AH;
typedef wmma::fragment<wmma::matrix_b, 16, 16, 16, __half, wmma::row_major> BH;

__global__ void __launch_bounds__(512, 1)
gemm_kernel(const __half* __restrict__ A, const __half* __restrict__ B,
            const float* __restrict__ bias, const float* __restrict__ Res,
            void* __restrict__ Cv, int M, int N, int K, int flags)
{
    extern __shared__ __align__(16) __half sh[];

    int tid = threadIdx.x;
    int warpId = tid >> 5;
    int wm = warpId & 3;                 // 0..3 along M (32 rows)
    int wn = warpId >> 2;                // 0..3 along N (64 cols)
    int rowBase = blockIdx.y * 128;
    int colBase = blockIdx.x * 256;

    wmma::fragment<wmma::accumulator, 16, 16, 16, float> acc[2][4];
    #pragma unroll
    for (int i = 0; i < 2; i++)
        #pragma unroll
        for (int j = 0; j < 4; j++) wmma::fill_fragment(acc[i][j], 0.0f);

    int nk = K / 64;

    #pragma unroll
    for (int s = 0; s < NSTG - 1; s++) {
        g_loadA(sh + s * STG_H,        A, rowBase, s * 64, K);
        g_loadB(sh + s * STG_H + AS_H, B, colBase, s * 64, N);
        cp_commit();
    }

    for (int kc = 0; kc < nk; kc++) {
        int buf = kc % NSTG;
        __half* As = sh + buf * STG_H;
        __half* Bs = As + AS_H;

        cp_wait<NSTG - 2>();
        __syncthreads();

        int pf = kc + NSTG - 1;
        if (pf < nk) {
            int pbuf = pf % NSTG;
            g_loadA(sh + pbuf * STG_H,        A, rowBase, pf * 64, K);
            g_loadB(sh + pbuf * STG_H + AS_H, B, colBase, pf * 64, N);
        }
        cp_commit();

        #pragma unroll
        for (int kk = 0; kk < 4; kk++) {
            AH af[2]; BH bf[4];
            #pragma unroll
            for (int i = 0; i < 2; i++)
                wmma::load_matrix_sync(af[i], &As[(wm * 32 + i * 16) * 72 + kk * 16], 72);
            #pragma unroll
            for (int j = 0; j < 4; j++)
                wmma::load_matrix_sync(bf[j], &Bs[kk * 16 * 264 + wn * 64 + j * 16], 264);
            #pragma unroll
            for (int i = 0; i < 2; i++)
                #pragma unroll
                for (int j = 0; j < 4; j++)
                    wmma::mma_sync(acc[i][j], af[i], bf[j], acc[i][j]);
        }
    }
    __syncthreads();

    // Epilogue: 4 quarters of 64 cols, staged via SMEM (fp32 staging).
    float* stag = (float*)sh;            // [128][68]
    int do_gelu = flags & 1, out_half = flags & 2, out_rtf = flags & 4;
    float* Cf = (float*)Cv;
    __half* Ch = (__half*)Cv;
    for (int qq = 0; qq < 4; qq++) {
        if (wn == qq) {
            #pragma unroll
            for (int i = 0; i < 2; i++)
                #pragma unroll
                for (int j = 0; j < 4; j++)
                    wmma::store_matrix_sync(&stag[(wm * 32 + i * 16) * 68 + j * 16],
                                            acc[i][j], 68, wmma::mem_row_major);
        }
        __syncthreads();
        #pragma unroll
        for (int i = 0; i < 4; i++) {
            int id = tid + i * 512;      // 0..2047 -> 128 rows x 16 float4
            int r = id >> 4, j = id & 15;
            int cg = colBase + qq * 64 + j * 4;
            size_t off = (size_t)(rowBase + r) * N + cg;
            float4 v = *(float4*)&stag[r * 68 + j * 4];
            float4 bb = *(const float4*)&bias[cg];
            v.x += bb.x; v.y += bb.y; v.z += bb.z; v.w += bb.w;
            if (do_gelu) {
                v.x = 0.5f * v.x * (1.0f + erff(v.x * 0.70710678118654752f));
                v.y = 0.5f * v.y * (1.0f + erff(v.y * 0.70710678118654752f));
                v.z = 0.5f * v.z * (1.0f + erff(v.z * 0.70710678118654752f));
                v.w = 0.5f * v.w * (1.0f + erff(v.w * 0.70710678118654752f));
            }
            if (Res) {
                float4 rv = *(const float4*)&Res[off];
                v.x += rv.x; v.y += rv.y; v.z += rv.z; v.w += rv.w;
            }
            if (out_half) {
                *(uint2*)&Ch[off] = pack4h(v.x, v.y, v.z, v.w);
            } else {
                if (out_rtf) { v.x = rtf(v.x); v.y = rtf(v.y); v.z = rtf(v.z); v.w = rtf(v.w); }
                *(float4*)&Cf[off] = v;
            }
        }
        __syncthreads();
    }
}

// ---------------------------------------------------------------------------
// Batched attention scores (tf32 wmma, proven R4 kernel):
// S[bh, t, s] = Q[t,:] . K[s,:]  (Q/K pre-rounded tf32 -> no in-loop cvt)
// ---------------------------------------------------------------------------
template<bool WIN>
__global__ void score_kernel(const float* __restrict__ Q, const float* __restrict__ Kmat,
                             float* __restrict__ S)
{
    __shared__ float sh[9216];
    float* Qs = sh;              // [128][36]
    float* Ks = sh + 4608;       // [128][36]
    int tid = threadIdx.x;
    int warpId = tid >> 5, wm = warpId & 3, wn = warpId >> 2;
    int bh = blockIdx.y;
    int b = bh / NH, h = bh % NH;
    int tx = blockIdx.x & 1, ty = blockIdx.x >> 1;

    wmma::fragment<wmma::accumulator, 16, 16, 8, float> acc[2][4];
    #pragma unroll
    for (int i = 0; i < 2; i++)
        #pragma unroll
        for (int j = 0; j < 4; j++) wmma::fill_fragment(acc[i][j], 0.0f);

    for (int kc = 0; kc < HD; kc += 32) {
        #pragma unroll
        for (int i = 0; i < 4; i++) {
            int id = tid + i * 256;
            int r = id >> 3, c = (id & 7) * 4;
            int t = ty * 128 + r;
            int grow = WIN ? wmap(b, t) : (b * TOK + t);
            *(float4*)&Qs[r * 36 + c] =
                *(const float4*)&Q[(size_t)grow * DMODEL + h * HD + kc + c];
        }
        #pragma unroll
        for (int i = 0; i < 4; i++) {
            int id = tid + i * 256;
            int r = id >> 3, c = (id & 7) * 4;
            int s = tx * 128 + r;
            int grow = WIN ? wmap(b, s) : (b * TOK + s);
            *(float4*)&Ks[r * 36 + c] =
                *(const float4*)&Kmat[(size_t)grow * DMODEL + h * HD + kc + c];
        }
        __syncthreads();
        #pragma unroll
        for (int kk = 0; kk < 4; kk++) {
            wmma::fragment<wmma::matrix_a, 16, 16, 8, wmma::precision::tf32, wmma::row_major> af[2];
            wmma::fragment<wmma::matrix_b, 16, 16, 8, wmma::precision::tf32, wmma::col_major> bf[4];
            #pragma unroll
            for (int i = 0; i < 2; i++)
                wmma::load_matrix_sync(af[i], &Qs[(wm * 32 + i * 16) * 36 + kk * 8], 36);
            #pragma unroll
            for (int j = 0; j < 4; j++)
                wmma::load_matrix_sync(bf[j], &Ks[(wn * 64 + j * 16) * 36 + kk * 8], 36);
            #pragma unroll
            for (int i = 0; i < 2; i++)
                #pragma unroll
                for (int j = 0; j < 4; j++)
                    wmma::mma_sync(acc[i][j], af[i], bf[j], acc[i][j]);
        }
        __syncthreads();
    }
    size_t base = (size_t)bh * (TOK * TOK);
    #pragma unroll
    for (int i = 0; i < 2; i++)
        #pragma unroll
        for (int j = 0; j < 4; j++)
            wmma::store_matrix_sync(
                &S[base + (size_t)(ty * 128 + wm * 32 + i * 16) * TOK
                       + tx * 128 + wn * 64 + j * 16],
                acc[i][j], TOK, wmma::mem_row_major);
}

// ---------------------------------------------------------------------------
// Softmax over 256-long rows (in-place, tf32-rounded output; proven R4)
// ---------------------------------------------------------------------------
__global__ void softmax_kernel(float* __restrict__ S, const int* __restrict__ mask)
{
    __shared__ float wred[8];
    int row = blockIdx.x, tid = threadIdx.x, lane = tid & 31, wrp = tid >> 5;
    int t = row & 255;
    size_t idx = (size_t)row * 256 + tid;
    float v = S[idx] * 0.125f;
    if (mask && mask[t * 256 + tid] == 0) v = -INFINITY;
    float m = v;
    #pragma unroll
    for (int o = 16; o > 0; o >>= 1) m = fmaxf(m, __shfl_xor_sync(0xffffffffu, m, o));
    if (lane == 0) wred[wrp] = m;
    __syncthreads();
    float mx = wred[lane & 7];
    #pragma unroll
    for (int o = 4; o > 0; o >>= 1) mx = fmaxf(mx, __shfl_xor_sync(0xffffffffu, mx, o));
    float e = __expf(v - mx);
    float sum = e;
    #pragma unroll
    for (int o = 16; o > 0; o >>= 1) sum += __shfl_xor_sync(0xffffffffu, sum, o);
    __syncthreads();
    if (lane == 0) wred[wrp] = sum;
    __syncthreads();
    float ts = wred[lane & 7];
    #pragma unroll
    for (int o = 4; o > 0; o >>= 1) ts += __shfl_xor_sync(0xffffffffu, ts, o);
    S[idx] = rtf(e / ts);
}

// ---------------------------------------------------------------------------
// Batched PV (tf32 wmma, proven R4) with fused window scatter; writes HALF
// (output feeds the fp16 O-projection GEMM).
// ---------------------------------------------------------------------------
template<bool WIN>
__global__ void pv_kernel(const float* __restrict__ S, const float* __restrict__ V,
                          __half* __restrict__ Y)
{
    __shared__ float sh[8704];
    float* As = sh;                      // [128][36]
    float* Bs = sh + 4608;               // [32][68]
    int tid = threadIdx.x;
    int warpId = tid >> 5, wm = warpId & 3, wn = warpId >> 2;
    int bh = blockIdx.y;
    int b = bh / NH, h = bh % NH;
    int ty = blockIdx.x;

    wmma::fragment<wmma::accumulator, 16, 16, 8, float> acc[2][2];
    #pragma unroll
    for (int i = 0; i < 2; i++)
        #pragma unroll
        for (int j = 0; j < 2; j++) wmma::fill_fragment(acc[i][j], 0.0f);

    size_t sbase = (size_t)bh * (TOK * TOK);
    for (int kc = 0; kc < TOK; kc += 32) {
        #pragma unroll
        for (int i = 0; i < 4; i++) {
            int id = tid + i * 256;
            int r = id >> 3, c = (id & 7) * 4;
            *(float4*)&As[r * 36 + c] =
                *(const float4*)&S[sbase + (size_t)(ty * 128 + r) * TOK + kc + c];
        }
        #pragma unroll
        for (int i = 0; i < 2; i++) {
            int id = tid + i * 256;
            int r = id >> 4, c = (id & 15) * 4;
            int s = kc + r;
            int grow = WIN ? wmap(b, s) : (b * TOK + s);
            *(float4*)&Bs[r * 68 + c] =
                *(const float4*)&V[(size_t)grow * DMODEL + h * HD + c];
        }
        __syncthreads();
        #pragma unroll
        for (int kk = 0; kk < 4; kk++) {
            wmma::fragment<wmma::matrix_a, 16, 16, 8, wmma::precision::tf32, wmma::row_major> af[2];
            wmma::fragment<wmma::matrix_b, 16, 16, 8, wmma::precision::tf32, wmma::row_major> bf[2];
            #pragma unroll
            for (int i = 0; i < 2; i++)
                wmma::load_matrix_sync(af[i], &As[(wm * 32 + i * 16) * 36 + kk * 8], 36);
            #pragma unroll
            for (int j = 0; j < 2; j++)
                wmma::load_matrix_sync(bf[j], &Bs[(kk * 8) * 68 + wn * 32 + j * 16], 68);
            #pragma unroll
            for (int i = 0; i < 2; i++)
                #pragma unroll
                for (int j = 0; j < 2; j++)
                    wmma::mma_sync(acc[i][j], af[i], bf[j], acc[i][j]);
        }
        __syncthreads();
    }

    float* stag = sh;                    // [128][68]
    #pragma unroll
    for (int i = 0; i < 2; i++)
        #pragma unroll
        for (int j = 0; j < 2; j++)
            wmma::store_matrix_sync(&stag[(wm * 32 + i * 16) * 68 + wn * 32 + j * 16],
                                    acc[i][j], 68, wmma::mem_row_major);
    __syncthreads();
    #pragma unroll
    for (int i = 0; i < 32; i++) {
        int id = tid + i * 256;
        int r = id >> 6, c = id & 63;
        int t = ty * 128 + r;
        int grow = WIN ? wmap(b, t) : (b * TOK + t);
        Y[(size_t)grow * DMODEL + h * HD + c] = __float2half_rn(stag[r * 68 + c]);
    }
}

// ---------------------------------------------------------------------------
// Launch sequence
// ---------------------------------------------------------------------------
extern "C" void kernel_launch(void* const* d_in, const int* in_sizes, int n_in,
                              void* d_out, int out_size)
{
    (void)in_sizes; (void)n_in; (void)out_size;
    const float* x    = (const float*)d_in[0];
    const int*   mask = (const int*)  d_in[1];
    const float* ln1g = (const float*)d_in[2];
    const float* ln1b = (const float*)d_in[3];
    const float* ln2g = (const float*)d_in[4];
    const float* ln2b = (const float*)d_in[5];
    const float* ln3g = (const float*)d_in[6];
    const float* ln3b = (const float*)d_in[7];
    const float* q1w = (const float*)d_in[8];  const float* q1b = (const float*)d_in[9];
    const float* k1w = (const float*)d_in[10]; const float* k1b = (const float*)d_in[11];
    const float* v1w = (const float*)d_in[12]; const float* v1b = (const float*)d_in[13];
    const float* o1w = (const float*)d_in[14]; const float* o1b = (const float*)d_in[15];
    const float* q2w = (const float*)d_in[16]; const float* q2b = (const float*)d_in[17];
    const float* k2w = (const float*)d_in[18]; const float* k2b = (const float*)d_in[19];
    const float* v2w = (const float*)d_in[20]; const float* v2b = (const float*)d_in[21];
    const float* o2w = (const float*)d_in[22]; const float* o2b = (const float*)d_in[23];
    const float* f1w = (const float*)d_in[24]; const float* f1b = (const float*)d_in[25];
    const float* f2w = (const float*)d_in[26]; const float* f2b = (const float*)d_in[27];
    float* out = (float*)d_out;

    __half *ln, *y, *mid, *wt;
    float *q, *k, *v, *s, *x1, *x2;
    cudaGetSymbolAddress((void**)&ln,  g_ln);
    cudaGetSymbolAddress((void**)&q,   g_q);
    cudaGetSymbolAddress((void**)&k,   g_k);
    cudaGetSymbolAddress((void**)&v,   g_v);
    cudaGetSymbolAddress((void**)&y,   g_y);
    cudaGetSymbolAddress((void**)&mid, g_mid);
    cudaGetSymbolAddress((void**)&s,   g_s);
    cudaGetSymbolAddress((void**)&x1,  g_x1);
    cudaGetSymbolAddress((void**)&x2,  g_x2);
    cudaGetSymbolAddress((void**)&wt,  g_wt);

    cudaFuncSetAttribute(gemm_kernel, cudaFuncAttributeMaxDynamicSharedMemorySize, GEMM_DSMEM);

    // Convert all weights to half
    const float* Ws[8] = {q1w, k1w, v1w, o1w, q2w, k2w, v2w, o2w};
    for (int i = 0; i < 8; i++)
        cvt_half<<<576, 256>>>(Ws[i], wt + WT_D(i), 147456);
    cvt_half<<<2304, 256>>>(f1w, wt + WT_F1, 589824);
    cvt_half<<<2304, 256>>>(f2w, wt + WT_F2, 589824);

    dim3 blk5(512);
    dim3 blk(256);
    dim3 gD(DMODEL / 256, ROWS / 128);   // (3, 256)
    dim3 gF1(DFF / 256, ROWS / 128);     // (12, 256)

    // flags: 1 gelu, 2 half out, 4 tf32-round fp32 out
    // ---- Block 1: full attention ----
    ln_kernel<<<ROWS, 256>>>(x, ln1g, ln1b, ln);
    gemm_kernel<<<gD, blk5, GEMM_DSMEM>>>(ln, wt + WT_D(0), q1b, nullptr, q, ROWS, DMODEL, DMODEL, 4);
    gemm_kernel<<<gD, blk5, GEMM_DSMEM>>>(ln, wt + WT_D(1), k1b, nullptr, k, ROWS, DMODEL, DMODEL, 4);
    gemm_kernel<<<gD, blk5, GEMM_DSMEM>>>(ln, wt + WT_D(2), v1b, nullptr, v, ROWS, DMODEL, DMODEL, 4);
    score_kernel<false><<<dim3(4, BHN), blk>>>(q, k, s);
    softmax_kernel<<<BHN * TOK, 256>>>(s, mask);
    pv_kernel<false><<<dim3(2, BHN), blk>>>(s, v, y);
    gemm_kernel<<<gD, blk5, GEMM_DSMEM>>>(y, wt + WT_D(3), o1b, x, x1, ROWS, DMODEL, DMODEL, 0);

    // ---- Block 2: window attention (permutation via index map) ----
    ln_kernel<<<ROWS, 256>>>(x1, ln2g, ln2b, ln);
    gemm_kernel<<<gD, blk5, GEMM_DSMEM>>>(ln, wt + WT_D(4), q2b, nullptr, q, ROWS, DMODEL, DMODEL, 4);
    gemm_kernel<<<gD, blk5, GEMM_DSMEM>>>(ln, wt + WT_D(5), k2b, nullptr, k, ROWS, DMODEL, DMODEL, 4);
    gemm_kernel<<<gD, blk5, GEMM_DSMEM>>>(ln, wt + WT_D(6), v2b, nullptr, v, ROWS, DMODEL, DMODEL, 4);
    score_kernel<true><<<dim3(4, BHN), blk>>>(q, k, s);
    softmax_kernel<<<BHN * TOK, 256>>>(s, nullptr);
    pv_kernel<true><<<dim3(2, BHN), blk>>>(s, v, y);
    gemm_kernel<<<gD, blk5, GEMM_DSMEM>>>(y, wt + WT_D(7), o2b, x1, x2, ROWS, DMODEL, DMODEL, 0);

    // ---- MLP ----
    ln_kernel<<<ROWS, 256>>>(x2, ln3g, ln3b, ln);
    gemm_kernel<<<gF1, blk5, GEMM_DSMEM>>>(ln, wt + WT_F1, f1b, nullptr, mid, ROWS, DFF, DMODEL, 3);
    gemm_kernel<<<gD, blk5, GEMM_DSMEM>>>(mid, wt + WT_F2, f2b, x2, out, ROWS, DMODEL, DFF, 0);
}